// round 1
// baseline (speedup 1.0000x reference)
#include <cuda_runtime.h>
#include <math.h>

#define BB 4
#define CC 64
#define WW 128
#define HH 128
#define KK 9
#define OCC 64
#define GG 16
#define EPSF 1e-5f
#define WH (WW*HH)

// ---- scratch (device globals; no allocation allowed) ----
__device__ float g_y[BB*KK*WW*HH];      // sampling y-coords  (2.4 MB)
__device__ float g_z[BB*OCC*WW*HH];     // pre-GN conv output (16.8 MB)
__device__ float g_gsum[BB*GG];
__device__ float g_gsq [BB*GG];

// linspace(-5, 4, 9): exact multiples of 0.125
__constant__ float c_lin[KK] = {-5.0f, -3.875f, -2.75f, -1.625f, -0.5f,
                                 0.625f, 1.75f, 2.875f, 4.0f};

__global__ void zero_stats_kernel() {
    int i = threadIdx.x;
    if (i < BB*GG) { g_gsum[i] = 0.f; g_gsq[i] = 0.f; }
}

// ---------------------------------------------------------------------------
// Kernel A: 3x3 offset conv (first K channels only) + BN + tanh + center-out
// cumulative offsets -> store absolute y sampling coordinate per (b,k,w,h).
// ---------------------------------------------------------------------------
__global__ void __launch_bounds__(128) offset_kernel(
    const float* __restrict__ f,
    const float* __restrict__ ow,   // (18, C, 3, 3) -- use first 9 out-ch
    const float* __restrict__ ob,
    const float* __restrict__ bn_g,
    const float* __restrict__ bn_b,
    const float* __restrict__ bn_m,
    const float* __restrict__ bn_v)
{
    __shared__ float sA[CC*9*KK];   // layout [(c*9 + t)*9 + k], t = r*3+s
    int tid = threadIdx.x;
    for (int i = tid; i < CC*9*KK; i += 128) {
        int c = i / 81, rem = i % 81, t = rem / 9, k = rem % 9;
        sA[i] = ow[(k*CC + c)*9 + t];
    }
    __syncthreads();

    int gidx = blockIdx.x * 128 + tid;           // over B*W*H
    int h = gidx % HH;
    int w = (gidx / HH) % WW;
    int b = gidx / (WW*HH);

    float acc[KK];
    #pragma unroll
    for (int k = 0; k < KK; k++) acc[k] = 0.f;

    const float* fb = f + b*CC*WH;
    #pragma unroll
    for (int r = 0; r < 3; r++) {
        int y = w + r - 1;
        if ((unsigned)y >= (unsigned)WW) continue;
        #pragma unroll
        for (int s = 0; s < 3; s++) {
            int x = h + s - 1;
            if ((unsigned)x >= (unsigned)HH) continue;
            int t = r*3 + s;
            const float* fp = fb + y*HH + x;
            #pragma unroll 4
            for (int c = 0; c < CC; c++) {
                float v = __ldg(fp + c*WH);
                const float* wp = &sA[(c*9 + t)*9];
                #pragma unroll
                for (int k = 0; k < KK; k++) acc[k] += v * wp[k];
            }
        }
    }

    float offs[KK];
    #pragma unroll
    for (int k = 0; k < KK; k++) {
        float sc  = rsqrtf(__ldg(bn_v + k) + EPSF);
        float val = (acc[k] + __ldg(ob + k) - __ldg(bn_m + k)) * sc;
        val = val * __ldg(bn_g + k) + __ldg(bn_b + k);
        offs[k] = tanhf(val);
    }

    // center-out cumulative sums; endpoints (k=0, k=8) stay RAW (reference quirk)
    float nw[KK];
    nw[4] = 0.f;
    nw[5] = 0.f + offs[5];  nw[6] = nw[5] + offs[6];  nw[7] = nw[6] + offs[7];
    nw[3] = 0.f + offs[3];  nw[2] = nw[3] + offs[2];  nw[1] = nw[2] + offs[1];
    nw[0] = offs[0];
    nw[8] = offs[8];

    #pragma unroll
    for (int k = 0; k < KK; k++)
        g_y[((b*KK + k)*WW + w)*HH + h] = (float)w + nw[k];   // EXTEND_SCOPE = 1
}

// ---------------------------------------------------------------------------
// Kernel B: fused bilinear deformable gather + (OC x C*K) matvec per pixel,
// + conv bias, write z, accumulate GroupNorm stats.
// Grid: (W, B, 2); block 128 threads (one thread per h); each block does 32 oc.
// ---------------------------------------------------------------------------
__global__ void __launch_bounds__(128) dsconv_main_kernel(
    const float* __restrict__ f,
    const float* __restrict__ cw,   // (OC, C, K, 1)
    const float* __restrict__ cb)
{
    extern __shared__ float sw[];   // [ (k*CC + c)*32 + j ]  (72 KB)
    int tid = threadIdx.x;
    int w = blockIdx.x, b = blockIdx.y;
    int ocbase = blockIdx.z * 32;

    for (int i = tid; i < KK*CC*32; i += 128) {
        int k = i >> 11;            // / 2048
        int rem = i & 2047;
        int c = rem >> 5;
        int j = rem & 31;
        sw[i] = cw[((ocbase + j)*CC + c)*KK + k];
    }
    __syncthreads();

    int h = tid;
    float acc[32];
    #pragma unroll
    for (int j = 0; j < 32; j++) acc[j] = 0.f;

    const float* fb = f + b*CC*WH;

    #pragma unroll
    for (int k = 0; k < KK; k++) {
        float ys = g_y[((b*KK + k)*WW + w)*HH + h];
        float xs = (float)h + c_lin[k];

        int y0 = (int)floorf(ys); y0 = max(0, min(y0, WW-1));
        int y1 = min(y0 + 1, WW-1);
        int x0 = (int)floorf(xs); x0 = max(0, min(x0, HH-1));
        int x1 = min(x0 + 1, HH-1);

        float wy0 = ys - (float)y0, wy1 = (float)y1 - ys;
        float wx0 = xs - (float)x0, wx1 = (float)x1 - xs;
        float w00 = wy1*wx1, w01 = wy1*wx0, w10 = wy0*wx1, w11 = wy0*wx0;

        int i00 = y0*HH + x0, i01 = y0*HH + x1;
        int i10 = y1*HH + x0, i11 = y1*HH + x1;

        const float4* swk = (const float4*)&sw[(k*CC)*32];

        #pragma unroll 2
        for (int c = 0; c < CC; c++) {
            const float* fc = fb + c*WH;
            float s = w00*__ldg(fc + i00) + w01*__ldg(fc + i01)
                    + w10*__ldg(fc + i10) + w11*__ldg(fc + i11);
            const float4* wp = swk + c*8;
            #pragma unroll
            for (int j4 = 0; j4 < 8; j4++) {
                float4 v = wp[j4];
                acc[j4*4+0] += s * v.x;
                acc[j4*4+1] += s * v.y;
                acc[j4*4+2] += s * v.z;
                acc[j4*4+3] += s * v.w;
            }
        }
    }

    // conv bias, write z, GroupNorm partial stats (groups of 4 channels)
    float gs[8], gq[8];
    #pragma unroll
    for (int j = 0; j < 8; j++) { gs[j] = 0.f; gq[j] = 0.f; }

    #pragma unroll
    for (int j = 0; j < 32; j++) {
        float z = acc[j] + __ldg(cb + ocbase + j);
        g_z[((b*OCC + ocbase + j)*WW + w)*HH + h] = z;
        gs[j >> 2] += z;
        gq[j >> 2] += z * z;
    }

    #pragma unroll
    for (int j = 0; j < 8; j++) {
        #pragma unroll
        for (int o = 16; o > 0; o >>= 1) {
            gs[j] += __shfl_xor_sync(0xffffffffu, gs[j], o);
            gq[j] += __shfl_xor_sync(0xffffffffu, gq[j], o);
        }
    }
    if ((tid & 31) == 0) {
        int gbase = b*GG + (ocbase >> 2);
        #pragma unroll
        for (int j = 0; j < 8; j++) {
            atomicAdd(&g_gsum[gbase + j], gs[j]);
            atomicAdd(&g_gsq [gbase + j], gq[j]);
        }
    }
}

// ---------------------------------------------------------------------------
// Kernel C: GroupNorm finalize + gamma/beta + ReLU
// ---------------------------------------------------------------------------
__global__ void __launch_bounds__(256) gn_kernel(
    const float* __restrict__ gn_g,
    const float* __restrict__ gn_b,
    float* __restrict__ out)
{
    int idx = blockIdx.x * 256 + threadIdx.x;
    if (idx >= BB*OCC*WW*HH) return;
    int oc = (idx / WH) % OCC;
    int b  = idx / (OCC*WH);
    int grp = b*GG + (oc >> 2);
    const float invn = 1.f / (float)(4*WH);  // 4 channels * W * H
    float mu  = g_gsum[grp] * invn;
    float var = g_gsq [grp] * invn - mu*mu;
    float z = g_z[idx];
    float v = (z - mu) * rsqrtf(var + EPSF) * __ldg(gn_g + oc) + __ldg(gn_b + oc);
    out[idx] = fmaxf(v, 0.f);
}

// ---------------------------------------------------------------------------
extern "C" void kernel_launch(void* const* d_in, const int* in_sizes, int n_in,
                              void* d_out, int out_size)
{
    const float* f        = (const float*)d_in[0];
    const float* offset_w = (const float*)d_in[1];
    const float* offset_b = (const float*)d_in[2];
    const float* bn_gamma = (const float*)d_in[3];
    const float* bn_beta  = (const float*)d_in[4];
    const float* bn_mean  = (const float*)d_in[5];
    const float* bn_var   = (const float*)d_in[6];
    const float* conv_w   = (const float*)d_in[7];
    const float* conv_b   = (const float*)d_in[8];
    const float* gn_gamma = (const float*)d_in[9];
    const float* gn_beta  = (const float*)d_in[10];
    float* out = (float*)d_out;

    static const size_t SMEM_B = (size_t)KK*CC*32*sizeof(float);  // 73728
    cudaFuncSetAttribute(dsconv_main_kernel,
                         cudaFuncAttributeMaxDynamicSharedMemorySize,
                         (int)SMEM_B);

    zero_stats_kernel<<<1, 64>>>();

    offset_kernel<<<(BB*WW*HH)/128, 128>>>(f, offset_w, offset_b,
                                           bn_gamma, bn_beta, bn_mean, bn_var);

    dim3 gridB(WW, BB, 2);
    dsconv_main_kernel<<<gridB, 128, SMEM_B>>>(f, conv_w, conv_b);

    int total = BB*OCC*WW*HH;
    gn_kernel<<<(total + 255)/256, 256>>>(gn_gamma, gn_beta, out);
}

// round 4
// speedup vs baseline: 3.0631x; 3.0631x over previous
#include <cuda_runtime.h>
#include <cuda_bf16.h>
#include <stdint.h>
#include <math.h>

#define BB 4
#define CC 64
#define WW 128
#define HH 128
#define KK 9
#define OCC 64
#define GG 16
#define EPSF 1e-5f
#define WH (WW*HH)

// ---- scratch (device globals; no allocation allowed) ----
__device__ float g_y[BB*KK*WW*HH];            // sampling y-coords
__device__ float g_z[BB*OCC*WW*HH];           // pre-GN conv output
__device__ float g_gsum[BB*GG];
__device__ float g_gsq [BB*GG];
// weight split: [k][p(hi/lo)][oc][c] bf16, 16B-aligned for uint4 copies
__device__ __align__(16) __nv_bfloat16 g_wsplit[KK*2*OCC*CC];

// linspace(-5, 4, 9): exact multiples of 0.125
__constant__ float c_lin[KK] = {-5.0f, -3.875f, -2.75f, -1.625f, -0.5f,
                                 0.625f, 1.75f, 2.875f, 4.0f};

static __device__ __forceinline__ uint32_t smem_u32(const void* p) {
    uint32_t a;
    asm("{ .reg .u64 t; cvta.to.shared.u64 t, %1; cvt.u32.u64 %0, t; }"
        : "=r"(a) : "l"(p));
    return a;
}

// ---- smem layout (padded rows: 72 bf16 = 144B stride -> conflict-free ldmatrix)
#define ROWB   144
#define SA_HI  0
#define SA_LO  (SA_HI + 128*ROWB)     // 18432
#define SB_HI  (SA_LO + 128*ROWB)     // 36864
#define SB_LO  (SB_HI + 64*ROWB)      // 46080
#define S_TOT  (SB_LO + 64*ROWB)      // 55296

#define LDSM_X4(r0,r1,r2,r3,addr) \
    asm volatile("ldmatrix.sync.aligned.m8n8.x4.shared.b16 {%0,%1,%2,%3}, [%4];" \
        : "=r"(r0), "=r"(r1), "=r"(r2), "=r"(r3) : "r"(addr))

#define MMA16816(d, a, b) \
    asm volatile("mma.sync.aligned.m16n8k16.row.col.f32.bf16.bf16.f32 " \
        "{%0,%1,%2,%3}, {%4,%5,%6,%7}, {%8,%9}, {%0,%1,%2,%3};" \
        : "+f"((d)[0]), "+f"((d)[1]), "+f"((d)[2]), "+f"((d)[3]) \
        : "r"((a)[0]), "r"((a)[1]), "r"((a)[2]), "r"((a)[3]), \
          "r"((b)[0]), "r"((b)[1]))

// ---------------------------------------------------------------------------
// Prep: split conv weights into bf16 hi/lo pieces, layout [k][p][oc][c].
// ---------------------------------------------------------------------------
__global__ void prep_w_kernel(const float* __restrict__ cw) {
    int i = blockIdx.x * 256 + threadIdx.x;      // over KK*OCC*CC
    if (i >= KK*OCC*CC) return;
    int k  = i / (OCC*CC);
    int oc = (i >> 6) & 63;
    int c  = i & 63;
    float v = cw[(oc*CC + c)*KK + k];
    __nv_bfloat16 hi = __float2bfloat16(v);
    __nv_bfloat16 lo = __float2bfloat16(v - __bfloat162float(hi));
    g_wsplit[((k*2 + 0)*OCC + oc)*CC + c] = hi;
    g_wsplit[((k*2 + 1)*OCC + oc)*CC + c] = lo;
}

// ---------------------------------------------------------------------------
// Kernel A: 3x3 offset conv (first K out-channels) + BN + tanh + center-out
// cumulative offsets -> absolute y sampling coordinate.
// ---------------------------------------------------------------------------
__global__ void __launch_bounds__(128) offset_kernel(
    const float* __restrict__ f,
    const float* __restrict__ ow,
    const float* __restrict__ ob,
    const float* __restrict__ bn_g,
    const float* __restrict__ bn_b,
    const float* __restrict__ bn_m,
    const float* __restrict__ bn_v)
{
    __shared__ float sA[CC*9*KK];   // [(c*9 + t)*9 + k]
    int tid = threadIdx.x;
    for (int i = tid; i < CC*9*KK; i += 128) {
        int c = i / 81, rem = i % 81, t = rem / 9, k = rem % 9;
        sA[i] = ow[(k*CC + c)*9 + t];
    }
    __syncthreads();

    int gidx = blockIdx.x * 128 + tid;
    int h = gidx % HH;
    int w = (gidx / HH) % WW;
    int b = gidx / (WW*HH);

    float acc[KK];
    #pragma unroll
    for (int k = 0; k < KK; k++) acc[k] = 0.f;

    const float* fb = f + b*CC*WH;
    #pragma unroll
    for (int r = 0; r < 3; r++) {
        int y = w + r - 1;
        if ((unsigned)y >= (unsigned)WW) continue;
        #pragma unroll
        for (int s = 0; s < 3; s++) {
            int x = h + s - 1;
            if ((unsigned)x >= (unsigned)HH) continue;
            int t = r*3 + s;
            const float* fp = fb + y*HH + x;
            #pragma unroll 4
            for (int c = 0; c < CC; c++) {
                float v = __ldg(fp + c*WH);
                const float* wp = &sA[(c*9 + t)*9];
                #pragma unroll
                for (int k = 0; k < KK; k++) acc[k] += v * wp[k];
            }
        }
    }

    float offs[KK];
    #pragma unroll
    for (int k = 0; k < KK; k++) {
        float sc  = rsqrtf(__ldg(bn_v + k) + EPSF);
        float val = (acc[k] + __ldg(ob + k) - __ldg(bn_m + k)) * sc;
        val = val * __ldg(bn_g + k) + __ldg(bn_b + k);
        offs[k] = tanhf(val);
    }

    // center-out cumsum; endpoints k=0, k=8 stay RAW (reference quirk)
    float nw[KK];
    nw[4] = 0.f;
    nw[5] = offs[5];  nw[6] = nw[5] + offs[6];  nw[7] = nw[6] + offs[7];
    nw[3] = offs[3];  nw[2] = nw[3] + offs[2];  nw[1] = nw[2] + offs[1];
    nw[0] = offs[0];
    nw[8] = offs[8];

    #pragma unroll
    for (int k = 0; k < KK; k++)
        g_y[((b*KK + k)*WW + w)*HH + h] = (float)w + nw[k];
}

// ---------------------------------------------------------------------------
// Kernel B: per (b,w) CTA, D[128h x 64oc] = sum_k G_k[128x64c] . W_k^T
// via warp-level HMMA (mma.sync m16n8k16 bf16, hi/lo split = 3 products).
// 8 warps, each owns a 32h x 32oc register tile accumulated across all taps.
// ---------------------------------------------------------------------------
__global__ void __launch_bounds__(256, 2) dsconv_mma_kernel(
    const float* __restrict__ f,
    const float* __restrict__ cb)
{
    extern __shared__ char smem[];
    uint32_t sb = smem_u32(smem);
    int tid  = threadIdx.x;
    int lane = tid & 31;
    int wid  = tid >> 5;
    int w = blockIdx.x, b = blockIdx.y;

    int mrow = (wid & 3) * 32;      // warp's h base (0,32,64,96)
    int ncol = (wid >> 2) * 32;     // warp's oc base (0,32)

    // per-thread gather assignment
    int h  = tid & 127;
    int ch = (tid >> 7) * 32;       // c range [ch, ch+32)

    // accumulators: d[mt][nt][4]
    float d[2][4][4];
    #pragma unroll
    for (int mt = 0; mt < 2; mt++)
        #pragma unroll
        for (int nt = 0; nt < 4; nt++)
            #pragma unroll
            for (int r = 0; r < 4; r++) d[mt][nt][r] = 0.f;

    const float* fb = f + b*CC*WH;

    // precompute lane-dependent ldmatrix address offsets
    // A: row = base + (lane & 15); colbyte += (lane>=16)?16:0
    uint32_t a_roff = (uint32_t)(lane & 15) * ROWB + ((lane & 16) ? 16u : 0u);
    // B: row = base + (lane & 7) + ((lane>=16)?8:0); colbyte += (lane&8)?16:0
    uint32_t b_roff = ((uint32_t)(lane & 7) + ((lane & 16) ? 8u : 0u)) * ROWB
                    + ((lane & 8) ? 16u : 0u);

    for (int k = 0; k < KK; k++) {
        __syncthreads();   // previous tap's ldmatrix reads done before overwrite

        // ---- copy weight tiles (hi+lo) into padded smem rows ----
        {
            const uint4* srcH = (const uint4*)(g_wsplit + (k*2 + 0)*OCC*CC);
            const uint4* srcL = (const uint4*)(g_wsplit + (k*2 + 1)*OCC*CC);
            #pragma unroll
            for (int t = 0; t < 2; t++) {
                int i = tid*2 + t;               // 0..511
                int oc = i >> 3, chunk = i & 7;
                *(uint4*)(smem + SB_HI + oc*ROWB + chunk*16) = srcH[i];
                *(uint4*)(smem + SB_LO + oc*ROWB + chunk*16) = srcL[i];
            }
        }

        // ---- bilinear gather + bf16 hi/lo split into A tile ----
        float ys = g_y[((b*KK + k)*WW + w)*HH + h];
        float xs = (float)h + c_lin[k];
        int y0 = (int)floorf(ys); y0 = max(0, min(y0, WW-1));
        int y1 = min(y0 + 1, WW-1);
        int x0 = (int)floorf(xs); x0 = max(0, min(x0, HH-1));
        int x1 = min(x0 + 1, HH-1);
        float wy0 = ys - (float)y0, wy1 = (float)y1 - ys;
        float wx0 = xs - (float)x0, wx1 = (float)x1 - xs;
        float w00 = wy1*wx1, w01 = wy1*wx0, w10 = wy0*wx1, w11 = wy0*wx0;
        int i00 = y0*HH + x0, i01 = y0*HH + x1;
        int i10 = y1*HH + x0, i11 = y1*HH + x1;

        char* Ahi = smem + SA_HI + h*ROWB;
        char* Alo = smem + SA_LO + h*ROWB;

        #pragma unroll 4
        for (int cc = 0; cc < 16; cc++) {
            int c0 = ch + cc*2;
            const float* f0 = fb + c0*WH;
            const float* f1 = f0 + WH;
            float s0 = w00*__ldg(f0+i00) + w01*__ldg(f0+i01)
                     + w10*__ldg(f0+i10) + w11*__ldg(f0+i11);
            float s1 = w00*__ldg(f1+i00) + w01*__ldg(f1+i01)
                     + w10*__ldg(f1+i10) + w11*__ldg(f1+i11);
            __nv_bfloat16 h0 = __float2bfloat16(s0);
            __nv_bfloat16 h1 = __float2bfloat16(s1);
            __nv_bfloat16 l0 = __float2bfloat16(s0 - __bfloat162float(h0));
            __nv_bfloat16 l1 = __float2bfloat16(s1 - __bfloat162float(h1));
            uint32_t hp = (uint32_t)__bfloat16_as_ushort(h0)
                        | ((uint32_t)__bfloat16_as_ushort(h1) << 16);
            uint32_t lp = (uint32_t)__bfloat16_as_ushort(l0)
                        | ((uint32_t)__bfloat16_as_ushort(l1) << 16);
            *(uint32_t*)(Ahi + c0*2) = hp;
            *(uint32_t*)(Alo + c0*2) = lp;
        }

        __syncthreads();

        // ---- HMMA over 4 k16 chunks ----
        #pragma unroll
        for (int kc = 0; kc < 4; kc++) {
            uint32_t colb = (uint32_t)kc * 32;

            uint32_t ah[2][4], al[2][4];
            #pragma unroll
            for (int mt = 0; mt < 2; mt++) {
                uint32_t ad = sb + SA_HI + (uint32_t)(mrow + mt*16)*ROWB
                            + a_roff + colb;
                LDSM_X4(ah[mt][0], ah[mt][1], ah[mt][2], ah[mt][3], ad);
                ad += (uint32_t)(SA_LO - SA_HI);
                LDSM_X4(al[mt][0], al[mt][1], al[mt][2], al[mt][3], ad);
            }

            uint32_t bh[4][2], bl[4][2];
            #pragma unroll
            for (int half = 0; half < 2; half++) {
                uint32_t bd = sb + SB_HI + (uint32_t)(ncol + half*16)*ROWB
                            + b_roff + colb;
                LDSM_X4(bh[half*2][0], bh[half*2][1],
                        bh[half*2+1][0], bh[half*2+1][1], bd);
                bd += (uint32_t)(SB_LO - SB_HI);
                LDSM_X4(bl[half*2][0], bl[half*2][1],
                        bl[half*2+1][0], bl[half*2+1][1], bd);
            }

            #pragma unroll
            for (int mt = 0; mt < 2; mt++)
                #pragma unroll
                for (int nt = 0; nt < 4; nt++) {
                    MMA16816(d[mt][nt], ah[mt], bh[nt]);   // hi*hi
                    MMA16816(d[mt][nt], ah[mt], bl[nt]);   // hi*lo
                    MMA16816(d[mt][nt], al[mt], bh[nt]);   // lo*hi
                }
        }
    }

    // ---- epilogue: bias + store z ----
    int hr = lane >> 2;             // 0..7
    int op = (lane & 3) * 2;        // 0,2,4,6
    #pragma unroll
    for (int mt = 0; mt < 2; mt++) {
        int hh = mrow + mt*16 + hr;
        #pragma unroll
        for (int nt = 0; nt < 4; nt++) {
            int oc = ncol + nt*8 + op;
            float b0 = __ldg(cb + oc), b1 = __ldg(cb + oc + 1);
            float* z0 = g_z + ((b*OCC + oc  )*WW + w)*HH;
            float* z1 = g_z + ((b*OCC + oc+1)*WW + w)*HH;
            z0[hh]     = d[mt][nt][0] + b0;
            z1[hh]     = d[mt][nt][1] + b1;
            z0[hh + 8] = d[mt][nt][2] + b0;
            z1[hh + 8] = d[mt][nt][3] + b1;
        }
    }
}

// ---------------------------------------------------------------------------
// Kernel C1: GroupNorm statistics. One block per (b, group); the group's 4
// channels are contiguous in g_z -> linear reduction, no atomics.
// ---------------------------------------------------------------------------
__global__ void __launch_bounds__(256) gn_stats_kernel() {
    __shared__ float ss[64], sq[64];
    int grp = blockIdx.x;                 // 0..63  (= b*GG + g)
    const float4* base = (const float4*)(g_z + (size_t)grp * 4 * WH);
    int tid = threadIdx.x;
    float s = 0.f, q = 0.f;
    #pragma unroll 8
    for (int j = 0; j < 64; j++) {
        float4 v = __ldg(base + tid + j*256);
        s += v.x + v.y + v.z + v.w;
        q += v.x*v.x + v.y*v.y + v.z*v.z + v.w*v.w;
    }
    #pragma unroll
    for (int o = 16; o > 0; o >>= 1) {
        s += __shfl_xor_sync(0xffffffffu, s, o);
        q += __shfl_xor_sync(0xffffffffu, q, o);
    }
    if ((tid & 31) == 0) { ss[tid >> 5] = s; sq[tid >> 5] = q; }
    __syncthreads();
    if (tid == 0) {
        float ts = 0.f, tq = 0.f;
        #pragma unroll
        for (int i = 0; i < 8; i++) { ts += ss[i]; tq += sq[i]; }
        g_gsum[grp] = ts;
        g_gsq [grp] = tq;
    }
}

// ---------------------------------------------------------------------------
// Kernel C2: GroupNorm finalize + gamma/beta + ReLU (float4 vectorized)
// ---------------------------------------------------------------------------
__global__ void __launch_bounds__(256) gn_kernel(
    const float* __restrict__ gn_g,
    const float* __restrict__ gn_b,
    float* __restrict__ out)
{
    int i4 = blockIdx.x * 256 + threadIdx.x;
    if (i4 >= BB*OCC*WH/4) return;
    int base = i4 * 4;
    int oc = (base / WH) % OCC;
    int b  = base / (OCC*WH);
    int grp = b*GG + (oc >> 2);
    const float invn = 1.f / (float)(4*WH);
    float mu  = g_gsum[grp] * invn;
    float var = g_gsq [grp] * invn - mu*mu;
    float rs  = rsqrtf(var + EPSF);
    float sc = rs * __ldg(gn_g + oc);
    float sh = __ldg(gn_b + oc) - mu * sc;
    float4 z = ((const float4*)g_z)[i4];
    float4 o;
    o.x = fmaxf(z.x*sc + sh, 0.f);
    o.y = fmaxf(z.y*sc + sh, 0.f);
    o.z = fmaxf(z.z*sc + sh, 0.f);
    o.w = fmaxf(z.w*sc + sh, 0.f);
    ((float4*)out)[i4] = o;
}

// ---------------------------------------------------------------------------
extern "C" void kernel_launch(void* const* d_in, const int* in_sizes, int n_in,
                              void* d_out, int out_size)
{
    const float* f        = (const float*)d_in[0];
    const float* offset_w = (const float*)d_in[1];
    const float* offset_b = (const float*)d_in[2];
    const float* bn_gamma = (const float*)d_in[3];
    const float* bn_beta  = (const float*)d_in[4];
    const float* bn_mean  = (const float*)d_in[5];
    const float* bn_var   = (const float*)d_in[6];
    const float* conv_w   = (const float*)d_in[7];
    const float* conv_b   = (const float*)d_in[8];
    const float* gn_gamma = (const float*)d_in[9];
    const float* gn_beta  = (const float*)d_in[10];
    float* out = (float*)d_out;

    cudaFuncSetAttribute(dsconv_mma_kernel,
                         cudaFuncAttributeMaxDynamicSharedMemorySize, S_TOT);

    prep_w_kernel<<<(KK*OCC*CC + 255)/256, 256>>>(conv_w);

    offset_kernel<<<(BB*WW*HH)/128, 128>>>(f, offset_w, offset_b,
                                           bn_gamma, bn_beta, bn_mean, bn_var);

    dim3 gridB(WW, BB);
    dsconv_mma_kernel<<<gridB, 256, S_TOT>>>(f, conv_b);

    gn_stats_kernel<<<BB*GG, 256>>>();

    int total4 = BB*OCC*WH/4;
    gn_kernel<<<(total4 + 255)/256, 256>>>(gn_gamma, gn_beta, out);
}

// round 8
// speedup vs baseline: 3.6190x; 1.1815x over previous
#include <cuda_runtime.h>
#include <cuda_bf16.h>
#include <stdint.h>
#include <math.h>

#define BB 4
#define CC 64
#define WW 128
#define HH 128
#define KK 9
#define OCC 64
#define GG 16
#define EPSF 1e-5f
#define WH (WW*HH)

// ---- scratch (device globals; no allocation allowed) ----
__device__ float g_y[BB*KK*WW*HH];            // sampling y-coords
__device__ float g_z[BB*OCC*WW*HH];           // pre-GN conv output
__device__ float g_gsum[BB*GG];
__device__ float g_gsq [BB*GG];
// weight split: [k][p(hi/lo)][oc][c] bf16, 16B-aligned for uint4 copies
__device__ __align__(16) __nv_bfloat16 g_wsplit[KK*2*OCC*CC];

// linspace(-5, 4, 9): exact multiples of 0.125
__constant__ float c_lin[KK] = {-5.0f, -3.875f, -2.75f, -1.625f, -0.5f,
                                 0.625f, 1.75f, 2.875f, 4.0f};

static __device__ __forceinline__ uint32_t smem_u32(const void* p) {
    uint32_t a;
    asm("{ .reg .u64 t; cvta.to.shared.u64 t, %1; cvt.u32.u64 %0, t; }"
        : "=r"(a) : "l"(p));
    return a;
}

// ---- smem layout (padded rows: 72 bf16 = 144B stride -> conflict-free ldmatrix
//      AND conflict-free STS.128: addr/16 = 9*row + chunk, distinct mod 8)
#define ROWB   144
#define SA_HI  0
#define SA_LO  (SA_HI + 128*ROWB)     // 18432
#define SB_HI  (SA_LO + 128*ROWB)     // 36864
#define SB_LO  (SB_HI + 64*ROWB)      // 46080
#define S_TOT  (SB_LO + 64*ROWB)      // 55296

#define LDSM_X4(r0,r1,r2,r3,addr) \
    asm volatile("ldmatrix.sync.aligned.m8n8.x4.shared.b16 {%0,%1,%2,%3}, [%4];" \
        : "=r"(r0), "=r"(r1), "=r"(r2), "=r"(r3) : "r"(addr))

#define MMA16816(d, a, b) \
    asm volatile("mma.sync.aligned.m16n8k16.row.col.f32.bf16.bf16.f32 " \
        "{%0,%1,%2,%3}, {%4,%5,%6,%7}, {%8,%9}, {%0,%1,%2,%3};" \
        : "+f"((d)[0]), "+f"((d)[1]), "+f"((d)[2]), "+f"((d)[3]) \
        : "r"((a)[0]), "r"((a)[1]), "r"((a)[2]), "r"((a)[3]), \
          "r"((b)[0]), "r"((b)[1]))

// ---------------------------------------------------------------------------
// Prep: split conv weights into bf16 hi/lo pieces, layout [k][p][oc][c].
// ---------------------------------------------------------------------------
__global__ void prep_w_kernel(const float* __restrict__ cw) {
    int i = blockIdx.x * 256 + threadIdx.x;      // over KK*OCC*CC
    if (i >= KK*OCC*CC) return;
    int k  = i / (OCC*CC);
    int oc = (i >> 6) & 63;
    int c  = i & 63;
    float v = cw[(oc*CC + c)*KK + k];
    __nv_bfloat16 hi = __float2bfloat16(v);
    __nv_bfloat16 lo = __float2bfloat16(v - __bfloat162float(hi));
    g_wsplit[((k*2 + 0)*OCC + oc)*CC + c] = hi;
    g_wsplit[((k*2 + 1)*OCC + oc)*CC + c] = lo;
}

// ---------------------------------------------------------------------------
// Kernel A: 3x3 offset conv (first K out-channels) + BN + tanh + center-out
// cumulative offsets -> absolute y sampling coordinate. Zeroes GN stats.
// Weight rows padded to 12 floats (48B) -> vectorized LDS.
// ---------------------------------------------------------------------------
__global__ void __launch_bounds__(128) offset_kernel(
    const float* __restrict__ f,
    const float* __restrict__ ow,
    const float* __restrict__ ob,
    const float* __restrict__ bn_g,
    const float* __restrict__ bn_b,
    const float* __restrict__ bn_m,
    const float* __restrict__ bn_v)
{
    if (blockIdx.x == 0 && threadIdx.x < BB*GG) {
        g_gsum[threadIdx.x] = 0.f;
        g_gsq [threadIdx.x] = 0.f;
    }

    __shared__ __align__(16) float sA[CC*9*12];   // [(c*9 + t)*12 + k], padded
    int tid = threadIdx.x;
    for (int i = tid; i < CC*9*KK; i += 128) {
        int c = i / 81, rem = i % 81, t = rem / 9, k = rem % 9;
        sA[(c*9 + t)*12 + k] = ow[(k*CC + c)*9 + t];
    }
    __syncthreads();

    int gidx = blockIdx.x * 128 + tid;
    int h = gidx % HH;
    int w = (gidx / HH) % WW;
    int b = gidx / (WW*HH);

    float acc[KK];
    #pragma unroll
    for (int k = 0; k < KK; k++) acc[k] = 0.f;

    const float* fb = f + b*CC*WH;
    #pragma unroll
    for (int r = 0; r < 3; r++) {
        int y = w + r - 1;
        if ((unsigned)y >= (unsigned)WW) continue;
        #pragma unroll
        for (int s = 0; s < 3; s++) {
            int x = h + s - 1;
            if ((unsigned)x >= (unsigned)HH) continue;
            int t = r*3 + s;
            const float* fp = fb + y*HH + x;
            #pragma unroll 4
            for (int c = 0; c < CC; c++) {
                float v = __ldg(fp + c*WH);
                const float4* wp = (const float4*)&sA[(c*9 + t)*12];
                float4 q0 = wp[0], q1 = wp[1];
                float  w8 = sA[(c*9 + t)*12 + 8];
                acc[0] += v * q0.x;  acc[1] += v * q0.y;
                acc[2] += v * q0.z;  acc[3] += v * q0.w;
                acc[4] += v * q1.x;  acc[5] += v * q1.y;
                acc[6] += v * q1.z;  acc[7] += v * q1.w;
                acc[8] += v * w8;
            }
        }
    }

    float offs[KK];
    #pragma unroll
    for (int k = 0; k < KK; k++) {
        float sc  = rsqrtf(__ldg(bn_v + k) + EPSF);
        float val = (acc[k] + __ldg(ob + k) - __ldg(bn_m + k)) * sc;
        val = val * __ldg(bn_g + k) + __ldg(bn_b + k);
        offs[k] = tanhf(val);
    }

    // center-out cumsum; endpoints k=0, k=8 stay RAW (reference quirk)
    float nw[KK];
    nw[4] = 0.f;
    nw[5] = offs[5];  nw[6] = nw[5] + offs[6];  nw[7] = nw[6] + offs[7];
    nw[3] = offs[3];  nw[2] = nw[3] + offs[2];  nw[1] = nw[2] + offs[1];
    nw[0] = offs[0];
    nw[8] = offs[8];

    #pragma unroll
    for (int k = 0; k < KK; k++)
        g_y[((b*KK + k)*WW + w)*HH + h] = (float)w + nw[k];
}

// ---------------------------------------------------------------------------
// Kernel B: per (b,w) CTA, D[128h x 64oc] = sum_k G_k[128x64c] . W_k^T
// via warp-level HMMA (m16n8k16 bf16, hi/lo split = 3 products).
// 8 warps, each owns a 32h x 32oc register tile accumulated across all taps.
// Epilogue fuses bias + z store + GroupNorm partial stats (shuffle + atomics).
// ---------------------------------------------------------------------------
__global__ void __launch_bounds__(256, 2) dsconv_mma_kernel(
    const float* __restrict__ f,
    const float* __restrict__ cb)
{
    extern __shared__ char smem[];
    uint32_t sb = smem_u32(smem);
    int tid  = threadIdx.x;
    int lane = tid & 31;
    int wid  = tid >> 5;
    int w = blockIdx.x, b = blockIdx.y;

    int mrow = (wid & 3) * 32;      // warp's h base (0,32,64,96)
    int ncol = (wid >> 2) * 32;     // warp's oc base (0,32)

    // per-thread gather assignment
    int h  = tid & 127;
    int ch = (tid >> 7) * 32;       // c range [ch, ch+32)

    float d[2][4][4];
    #pragma unroll
    for (int mt = 0; mt < 2; mt++)
        #pragma unroll
        for (int nt = 0; nt < 4; nt++)
            #pragma unroll
            for (int r = 0; r < 4; r++) d[mt][nt][r] = 0.f;

    const float* fb = f + b*CC*WH;

    uint32_t a_roff = (uint32_t)(lane & 15) * ROWB + ((lane & 16) ? 16u : 0u);
    uint32_t b_roff = ((uint32_t)(lane & 7) + ((lane & 16) ? 8u : 0u)) * ROWB
                    + ((lane & 8) ? 16u : 0u);

    for (int k = 0; k < KK; k++) {
        __syncthreads();   // previous tap's ldmatrix reads done before overwrite

        // ---- copy weight tiles (hi+lo) into padded smem rows ----
        {
            const uint4* srcH = (const uint4*)(g_wsplit + (k*2 + 0)*OCC*CC);
            const uint4* srcL = (const uint4*)(g_wsplit + (k*2 + 1)*OCC*CC);
            #pragma unroll
            for (int t = 0; t < 2; t++) {
                int i = tid*2 + t;               // 0..511
                int oc = i >> 3, chunk = i & 7;
                *(uint4*)(smem + SB_HI + oc*ROWB + chunk*16) = srcH[i];
                *(uint4*)(smem + SB_LO + oc*ROWB + chunk*16) = srcL[i];
            }
        }

        // ---- bilinear gather + bf16 hi/lo split; STS.128 (conflict-free) ----
        float ys = g_y[((b*KK + k)*WW + w)*HH + h];
        float xs = (float)h + c_lin[k];
        int y0 = (int)floorf(ys); y0 = max(0, min(y0, WW-1));
        int y1 = min(y0 + 1, WW-1);
        int x0 = (int)floorf(xs); x0 = max(0, min(x0, HH-1));
        int x1 = min(x0 + 1, HH-1);
        float wy0 = ys - (float)y0, wy1 = (float)y1 - ys;
        float wx0 = xs - (float)x0, wx1 = (float)x1 - xs;
        float w00 = wy1*wx1, w01 = wy1*wx0, w10 = wy0*wx1, w11 = wy0*wx0;
        int i00 = y0*HH + x0, i01 = y0*HH + x1;
        int i10 = y1*HH + x0, i11 = y1*HH + x1;

        char* Ahi = smem + SA_HI + h*ROWB;
        char* Alo = smem + SA_LO + h*ROWB;

        #pragma unroll
        for (int c8 = 0; c8 < 4; c8++) {
            int c0 = ch + c8*8;
            uint32_t hp[4], lp[4];
            #pragma unroll
            for (int j = 0; j < 4; j++) {
                const float* f0 = fb + (c0 + j*2)*WH;
                const float* f1 = f0 + WH;
                float s0 = w00*__ldg(f0+i00) + w01*__ldg(f0+i01)
                         + w10*__ldg(f0+i10) + w11*__ldg(f0+i11);
                float s1 = w00*__ldg(f1+i00) + w01*__ldg(f1+i01)
                         + w10*__ldg(f1+i10) + w11*__ldg(f1+i11);
                __nv_bfloat16 h0 = __float2bfloat16(s0);
                __nv_bfloat16 h1 = __float2bfloat16(s1);
                __nv_bfloat16 l0 = __float2bfloat16(s0 - __bfloat162float(h0));
                __nv_bfloat16 l1 = __float2bfloat16(s1 - __bfloat162float(h1));
                hp[j] = (uint32_t)__bfloat16_as_ushort(h0)
                      | ((uint32_t)__bfloat16_as_ushort(h1) << 16);
                lp[j] = (uint32_t)__bfloat16_as_ushort(l0)
                      | ((uint32_t)__bfloat16_as_ushort(l1) << 16);
            }
            *(uint4*)(Ahi + c0*2) = make_uint4(hp[0], hp[1], hp[2], hp[3]);
            *(uint4*)(Alo + c0*2) = make_uint4(lp[0], lp[1], lp[2], lp[3]);
        }

        __syncthreads();

        // ---- HMMA over 4 k16 chunks ----
        #pragma unroll
        for (int kc = 0; kc < 4; kc++) {
            uint32_t colb = (uint32_t)kc * 32;

            uint32_t ah[2][4], al[2][4];
            #pragma unroll
            for (int mt = 0; mt < 2; mt++) {
                uint32_t ad = sb + SA_HI + (uint32_t)(mrow + mt*16)*ROWB
                            + a_roff + colb;
                LDSM_X4(ah[mt][0], ah[mt][1], ah[mt][2], ah[mt][3], ad);
                ad += (uint32_t)(SA_LO - SA_HI);
                LDSM_X4(al[mt][0], al[mt][1], al[mt][2], al[mt][3], ad);
            }

            uint32_t bh[4][2], bl[4][2];
            #pragma unroll
            for (int half = 0; half < 2; half++) {
                uint32_t bd = sb + SB_HI + (uint32_t)(ncol + half*16)*ROWB
                            + b_roff + colb;
                LDSM_X4(bh[half*2][0], bh[half*2][1],
                        bh[half*2+1][0], bh[half*2+1][1], bd);
                bd += (uint32_t)(SB_LO - SB_HI);
                LDSM_X4(bl[half*2][0], bl[half*2][1],
                        bl[half*2+1][0], bl[half*2+1][1], bd);
            }

            #pragma unroll
            for (int mt = 0; mt < 2; mt++)
                #pragma unroll
                for (int nt = 0; nt < 4; nt++) {
                    MMA16816(d[mt][nt], ah[mt], bh[nt]);   // hi*hi
                    MMA16816(d[mt][nt], ah[mt], bl[nt]);   // hi*lo
                    MMA16816(d[mt][nt], al[mt], bh[nt]);   // lo*hi
                }
        }
    }

    // ---- epilogue: bias + store z + fused GroupNorm partial stats ----
    int hr = lane >> 2;             // 0..7
    int op = (lane & 3) * 2;        // 0,2,4,6
    float gs[4], gq[4];
    #pragma unroll
    for (int nt = 0; nt < 4; nt++) { gs[nt] = 0.f; gq[nt] = 0.f; }

    #pragma unroll
    for (int mt = 0; mt < 2; mt++) {
        int hh = mrow + mt*16 + hr;
        #pragma unroll
        for (int nt = 0; nt < 4; nt++) {
            int oc = ncol + nt*8 + op;
            float b0 = __ldg(cb + oc), b1 = __ldg(cb + oc + 1);
            float* z0 = g_z + ((b*OCC + oc  )*WW + w)*HH;
            float* z1 = g_z + ((b*OCC + oc+1)*WW + w)*HH;
            float v0 = d[mt][nt][0] + b0;
            float v1 = d[mt][nt][1] + b1;
            float v2 = d[mt][nt][2] + b0;
            float v3 = d[mt][nt][3] + b1;
            z0[hh]     = v0;
            z1[hh]     = v1;
            z0[hh + 8] = v2;
            z1[hh + 8] = v3;
            gs[nt] += v0 + v1 + v2 + v3;
            gq[nt] += v0*v0 + v1*v1 + v2*v2 + v3*v3;
        }
    }

    // Reduce across the 16 lanes sharing a group: xor over {1,4,8,16}
    // preserves lane bit1 (which selects group parity via op>=4).
    #pragma unroll
    for (int nt = 0; nt < 4; nt++) {
        #pragma unroll
        for (int o = 0; o < 4; o++) {
            int m = (o == 0) ? 1 : (o == 1) ? 4 : (o == 2) ? 8 : 16;
            gs[nt] += __shfl_xor_sync(0xffffffffu, gs[nt], m);
            gq[nt] += __shfl_xor_sync(0xffffffffu, gq[nt], m);
        }
    }
    if ((lane & ~2) == 0) {          // lanes 0 and 2 are representatives
        int gpar = (lane >> 1) & 1;
        #pragma unroll
        for (int nt = 0; nt < 4; nt++) {
            int grp = b*GG + (ncol >> 2) + nt*2 + gpar;
            atomicAdd(&g_gsum[grp], gs[nt]);
            atomicAdd(&g_gsq [grp], gq[nt]);
        }
    }
}

// ---------------------------------------------------------------------------
// Kernel C: GroupNorm finalize + gamma/beta + ReLU (float4 vectorized)
// ---------------------------------------------------------------------------
__global__ void __launch_bounds__(256) gn_kernel(
    const float* __restrict__ gn_g,
    const float* __restrict__ gn_b,
    float* __restrict__ out)
{
    int i4 = blockIdx.x * 256 + threadIdx.x;
    if (i4 >= BB*OCC*WH/4) return;
    int base = i4 * 4;
    int oc = (base / WH) % OCC;
    int b  = base / (OCC*WH);
    int grp = b*GG + (oc >> 2);
    const float invn = 1.f / (float)(4*WH);
    float mu  = g_gsum[grp] * invn;
    float var = g_gsq [grp] * invn - mu*mu;
    float rs  = rsqrtf(var + EPSF);
    float sc = rs * __ldg(gn_g + oc);
    float sh = __ldg(gn_b + oc) - mu * sc;
    float4 z = ((const float4*)g_z)[i4];
    float4 o;
    o.x = fmaxf(z.x*sc + sh, 0.f);
    o.y = fmaxf(z.y*sc + sh, 0.f);
    o.z = fmaxf(z.z*sc + sh, 0.f);
    o.w = fmaxf(z.w*sc + sh, 0.f);
    ((float4*)out)[i4] = o;
}

// ---------------------------------------------------------------------------
extern "C" void kernel_launch(void* const* d_in, const int* in_sizes, int n_in,
                              void* d_out, int out_size)
{
    const float* f        = (const float*)d_in[0];
    const float* offset_w = (const float*)d_in[1];
    const float* offset_b = (const float*)d_in[2];
    const float* bn_gamma = (const float*)d_in[3];
    const float* bn_beta  = (const float*)d_in[4];
    const float* bn_mean  = (const float*)d_in[5];
    const float* bn_var   = (const float*)d_in[6];
    const float* conv_w   = (const float*)d_in[7];
    const float* conv_b   = (const float*)d_in[8];
    const float* gn_gamma = (const float*)d_in[9];
    const float* gn_beta  = (const float*)d_in[10];
    float* out = (float*)d_out;

    cudaFuncSetAttribute(dsconv_mma_kernel,
                         cudaFuncAttributeMaxDynamicSharedMemorySize, S_TOT);

    prep_w_kernel<<<(KK*OCC*CC + 255)/256, 256>>>(conv_w);

    offset_kernel<<<(BB*WW*HH)/128, 128>>>(f, offset_w, offset_b,
                                           bn_gamma, bn_beta, bn_mean, bn_var);

    dim3 gridB(WW, BB);
    dsconv_mma_kernel<<<gridB, 256, S_TOT>>>(f, conv_b);

    int total4 = BB*OCC*WH/4;
    gn_kernel<<<(total4 + 255)/256, 256>>>(gn_gamma, gn_beta, out);
}

// round 9
// speedup vs baseline: 3.8375x; 1.0604x over previous
#include <cuda_runtime.h>
#include <cuda_bf16.h>
#include <stdint.h>
#include <math.h>

#define BB 4
#define CC 64
#define WW 128
#define HH 128
#define KK 9
#define OCC 64
#define GG 16
#define EPSF 1e-5f
#define WH (WW*HH)

// ---- scratch (device globals; no allocation allowed) ----
__device__ float g_y[BB*KK*WW*HH];            // sampling y-coords
__device__ float g_z[BB*OCC*WW*HH];           // pre-GN conv output
__device__ float g_gsum[BB*GG];
__device__ float g_gsq [BB*GG];
// weight chunks: [(q*9+k)][p(hi/lo)][oc][24 bf16 (16 used, 48B padded rows)]
__device__ __align__(16) __nv_bfloat16 g_wq[36*2*OCC*24];

// linspace(-5, 4, 9): exact multiples of 0.125
__constant__ float c_lin[KK] = {-5.0f, -3.875f, -2.75f, -1.625f, -0.5f,
                                 0.625f, 1.75f, 2.875f, 4.0f};

static __device__ __forceinline__ uint32_t smem_u32(const void* p) {
    uint32_t a;
    asm("{ .reg .u64 t; cvta.to.shared.u64 t, %1; cvt.u32.u64 %0, t; }"
        : "=r"(a) : "l"(p));
    return a;
}

// ---- smem layout ----
// SF: staged f rows, [c_local(16)][slot(7)][x(128)] fp32 = 57344 B
// SA: A slices, 2 bufs x (hi 128x48B + lo 128x48B) = 2 x 12288
// SB: B chunks, 2 bufs x (hi 64x48B + lo 64x48B)   = 2 x 6144
#define SF_OFF  0
#define SA_OFF  57344
#define SB_OFF  (SA_OFF + 2*12288)     // 81920
#define S_TOT   (SB_OFF + 2*6144)      // 94208

#define LDSM_X4(r0,r1,r2,r3,addr) \
    asm volatile("ldmatrix.sync.aligned.m8n8.x4.shared.b16 {%0,%1,%2,%3}, [%4];" \
        : "=r"(r0), "=r"(r1), "=r"(r2), "=r"(r3) : "r"(addr))

#define MMA16816(d, a, b) \
    asm volatile("mma.sync.aligned.m16n8k16.row.col.f32.bf16.bf16.f32 " \
        "{%0,%1,%2,%3}, {%4,%5,%6,%7}, {%8,%9}, {%0,%1,%2,%3};" \
        : "+f"((d)[0]), "+f"((d)[1]), "+f"((d)[2]), "+f"((d)[3]) \
        : "r"((a)[0]), "r"((a)[1]), "r"((a)[2]), "r"((a)[3]), \
          "r"((b)[0]), "r"((b)[1]))

#define CP_ASYNC16(dst, src) \
    asm volatile("cp.async.ca.shared.global [%0], [%1], 16;" \
        :: "r"(dst), "l"(src) : "memory")
#define CP_COMMIT()  asm volatile("cp.async.commit_group;" ::: "memory")
#define CP_WAIT0()   asm volatile("cp.async.wait_group 0;" ::: "memory")

// ---------------------------------------------------------------------------
// Prep: split conv weights into bf16 hi/lo, quarter-chunk padded layout.
// ---------------------------------------------------------------------------
__global__ void prep_w_kernel(const float* __restrict__ cw) {
    int i = blockIdx.x * 256 + threadIdx.x;      // over KK*OCC*CC
    if (i >= KK*OCC*CC) return;
    int k  = i / (OCC*CC);
    int oc = (i >> 6) & 63;
    int c  = i & 63;
    float v = cw[(oc*CC + c)*KK + k];
    __nv_bfloat16 hi = __float2bfloat16(v);
    __nv_bfloat16 lo = __float2bfloat16(v - __bfloat162float(hi));
    int q  = c >> 4, cl = c & 15;
    int chunk = q*KK + k;
    g_wq[((chunk*2 + 0)*OCC + oc)*24 + cl] = hi;
    g_wq[((chunk*2 + 1)*OCC + oc)*24 + cl] = lo;
}

// ---------------------------------------------------------------------------
// Kernel A: 3x3 offset conv (first K out-channels) + BN + tanh + center-out
// cumulative offsets -> absolute y sampling coordinate. Zeroes GN stats.
// ---------------------------------------------------------------------------
__global__ void __launch_bounds__(128) offset_kernel(
    const float* __restrict__ f,
    const float* __restrict__ ow,
    const float* __restrict__ ob,
    const float* __restrict__ bn_g,
    const float* __restrict__ bn_b,
    const float* __restrict__ bn_m,
    const float* __restrict__ bn_v)
{
    if (blockIdx.x == 0 && threadIdx.x < BB*GG) {
        g_gsum[threadIdx.x] = 0.f;
        g_gsq [threadIdx.x] = 0.f;
    }

    __shared__ __align__(16) float sA[CC*9*12];   // [(c*9 + t)*12 + k], padded
    int tid = threadIdx.x;
    for (int i = tid; i < CC*9*KK; i += 128) {
        int c = i / 81, rem = i % 81, t = rem / 9, k = rem % 9;
        sA[(c*9 + t)*12 + k] = ow[(k*CC + c)*9 + t];
    }
    __syncthreads();

    int gidx = blockIdx.x * 128 + tid;
    int h = gidx % HH;
    int w = (gidx / HH) % WW;
    int b = gidx / (WW*HH);

    float acc[KK];
    #pragma unroll
    for (int k = 0; k < KK; k++) acc[k] = 0.f;

    const float* fb = f + b*CC*WH;
    #pragma unroll
    for (int r = 0; r < 3; r++) {
        int y = w + r - 1;
        if ((unsigned)y >= (unsigned)WW) continue;
        #pragma unroll
        for (int s = 0; s < 3; s++) {
            int x = h + s - 1;
            if ((unsigned)x >= (unsigned)HH) continue;
            int t = r*3 + s;
            const float* fp = fb + y*HH + x;
            #pragma unroll 4
            for (int c = 0; c < CC; c++) {
                float v = __ldg(fp + c*WH);
                const float4* wp = (const float4*)&sA[(c*9 + t)*12];
                float4 q0 = wp[0], q1 = wp[1];
                float  w8 = sA[(c*9 + t)*12 + 8];
                acc[0] += v * q0.x;  acc[1] += v * q0.y;
                acc[2] += v * q0.z;  acc[3] += v * q0.w;
                acc[4] += v * q1.x;  acc[5] += v * q1.y;
                acc[6] += v * q1.z;  acc[7] += v * q1.w;
                acc[8] += v * w8;
            }
        }
    }

    float offs[KK];
    #pragma unroll
    for (int k = 0; k < KK; k++) {
        float sc  = rsqrtf(__ldg(bn_v + k) + EPSF);
        float val = (acc[k] + __ldg(ob + k) - __ldg(bn_m + k)) * sc;
        val = val * __ldg(bn_g + k) + __ldg(bn_b + k);
        offs[k] = tanhf(val);
    }

    // center-out cumsum; endpoints k=0, k=8 stay RAW (reference quirk)
    float nw[KK];
    nw[4] = 0.f;
    nw[5] = offs[5];  nw[6] = nw[5] + offs[6];  nw[7] = nw[6] + offs[7];
    nw[3] = offs[3];  nw[2] = nw[3] + offs[2];  nw[1] = nw[2] + offs[1];
    nw[0] = offs[0];
    nw[8] = offs[8];

    #pragma unroll
    for (int k = 0; k < KK; k++)
        g_y[((b*KK + k)*WW + w)*HH + h] = (float)w + nw[k];
}

// ---------------------------------------------------------------------------
// Kernel B: per (b,w) CTA, D[128h x 64oc] = sum_k G_k[128x64c] . W_k^T.
// Staged-row gather: all sampling rows lie in [w-3, w+3] (cumsum of <=3 tanh),
// so per c-quarter we stage 16c x 7rows x 128x fp32 in smem (coalesced LDG),
// then bilinear-gather via conflict-free LDS. 36 phases (9 taps x 4 quarters),
// K=16 HMMA each, A/B double-buffered, B chunks via cp.async.
// ---------------------------------------------------------------------------
__global__ void __launch_bounds__(256, 2) dsconv_mma_kernel(
    const float* __restrict__ f,
    const float* __restrict__ cb)
{
    extern __shared__ char smem[];
    float* SFp = (float*)smem;
    uint32_t sb = smem_u32(smem);
    int tid  = threadIdx.x;
    int lane = tid & 31;
    int wid  = tid >> 5;
    int w = blockIdx.x, b = blockIdx.y;

    int mrow = (wid & 3) * 32;      // warp's h base
    int ncol = (wid >> 2) * 32;     // warp's oc base

    int h   = tid & 127;
    int sub = tid >> 7;             // which 8-channel half of the quarter

    float d[2][4][4];
    #pragma unroll
    for (int mt = 0; mt < 2; mt++)
        #pragma unroll
        for (int nt = 0; nt < 4; nt++)
            #pragma unroll
            for (int r = 0; r < 4; r++) d[mt][nt][r] = 0.f;

    // preload sampling coords for all taps (coalesced over h)
    float ysr[KK];
    #pragma unroll
    for (int k = 0; k < KK; k++)
        ysr[k] = g_y[((b*KK + k)*WW + w)*HH + h];

    const float* fb = f + b*CC*WH;

    // ldmatrix lane offsets for 48B-stride rows
    uint32_t a_roff = (uint32_t)(lane & 15) * 48 + ((lane & 16) ? 16u : 0u);
    uint32_t b_roff = ((uint32_t)(lane & 7) + ((lane & 16) ? 8u : 0u)) * 48
                    + ((lane & 8) ? 16u : 0u);

    int phase = 0;
    for (int q = 0; q < 4; q++) {
        // ---- stage 16 channels x 7 rows x 128 x (float4 coalesced) ----
        {
            const float* fq = fb + (q*16)*WH;
            #pragma unroll
            for (int j = 0; j < 14; j++) {
                int idx  = tid + j*256;            // 0..3583 float4s
                int cl   = idx / 224;
                int rem  = idx % 224;
                int slot = rem >> 5;
                int x4   = rem & 31;
                int row  = w - 3 + slot;
                row = max(0, min(row, WW-1));
                float4 v = __ldg((const float4*)(fq + cl*WH + row*HH) + x4);
                *((float4*)(SFp + (cl*7 + slot)*128) + x4) = v;
            }
        }
        __syncthreads();

        for (int k = 0; k < KK; k++) {
            int buf = phase & 1;

            // ---- B chunk via cp.async (hi+lo contiguous, 6144 B) ----
            {
                const char* src = (const char*)g_wq + (q*KK + k)*6144;
                uint32_t dst = sb + SB_OFF + buf*6144;
                #pragma unroll
                for (int i = 0; i < 2; i++) {
                    int t = tid + i*256;
                    if (t < 384) CP_ASYNC16(dst + t*16, src + t*16);
                }
                CP_COMMIT();
            }

            // ---- bilinear gather from staged rows (LDS, conflict-free) ----
            float ys = ysr[k];
            float xs = (float)h + c_lin[k];
            int y0 = (int)floorf(ys); y0 = max(0, min(y0, WW-1));
            int y1 = min(y0 + 1, WW-1);
            int x0 = (int)floorf(xs); x0 = max(0, min(x0, HH-1));
            int x1 = min(x0 + 1, HH-1);
            float wy0 = ys - (float)y0, wy1 = (float)y1 - ys;
            float wx0 = xs - (float)x0, wx1 = (float)x1 - xs;
            float w00 = wy1*wx1, w01 = wy1*wx0, w10 = wy0*wx1, w11 = wy0*wx0;

            int s00 = (y0 - (w-3))*128 + x0;
            int s01 = s00 + (x1 - x0);
            int s10 = (y1 - (w-3))*128 + x0;
            int s11 = s10 + (x1 - x0);

            const float* base = SFp + (sub*8)*7*128;
            uint32_t hp[4], lp[4];
            #pragma unroll
            for (int j = 0; j < 4; j++) {
                float sA0, sB0;
                {
                    float a00 = base[s00], a01 = base[s01];
                    float a10 = base[s10], a11 = base[s11];
                    sA0 = w00*a00 + w01*a01 + w10*a10 + w11*a11;
                    base += 896;
                    float b00 = base[s00], b01 = base[s01];
                    float b10 = base[s10], b11 = base[s11];
                    sB0 = w00*b00 + w01*b01 + w10*b10 + w11*b11;
                    base += 896;
                }
                __nv_bfloat16 h0 = __float2bfloat16(sA0);
                __nv_bfloat16 h1 = __float2bfloat16(sB0);
                __nv_bfloat16 l0 = __float2bfloat16(sA0 - __bfloat162float(h0));
                __nv_bfloat16 l1 = __float2bfloat16(sB0 - __bfloat162float(h1));
                hp[j] = (uint32_t)__bfloat16_as_ushort(h0)
                      | ((uint32_t)__bfloat16_as_ushort(h1) << 16);
                lp[j] = (uint32_t)__bfloat16_as_ushort(l0)
                      | ((uint32_t)__bfloat16_as_ushort(l1) << 16);
            }
            {
                char* Abase = smem + SA_OFF + buf*12288;
                *(uint4*)(Abase + h*48 + sub*16)
                    = make_uint4(hp[0], hp[1], hp[2], hp[3]);
                *(uint4*)(Abase + 6144 + h*48 + sub*16)
                    = make_uint4(lp[0], lp[1], lp[2], lp[3]);
            }

            CP_WAIT0();
            __syncthreads();

            // ---- HMMA: one K=16 chunk, hi/lo split (3 products) ----
            uint32_t abase = sb + SA_OFF + buf*12288;
            uint32_t bbase = sb + SB_OFF + buf*6144;

            uint32_t ah[2][4], al[2][4];
            #pragma unroll
            for (int mt = 0; mt < 2; mt++) {
                uint32_t ad = abase + (uint32_t)(mrow + mt*16)*48 + a_roff;
                LDSM_X4(ah[mt][0], ah[mt][1], ah[mt][2], ah[mt][3], ad);
                ad += 6144u;
                LDSM_X4(al[mt][0], al[mt][1], al[mt][2], al[mt][3], ad);
            }
            uint32_t bh[4][2], bl[4][2];
            #pragma unroll
            for (int half = 0; half < 2; half++) {
                uint32_t bd = bbase + (uint32_t)(ncol + half*16)*48 + b_roff;
                LDSM_X4(bh[half*2][0], bh[half*2][1],
                        bh[half*2+1][0], bh[half*2+1][1], bd);
                bd += 3072u;
                LDSM_X4(bl[half*2][0], bl[half*2][1],
                        bl[half*2+1][0], bl[half*2+1][1], bd);
            }
            #pragma unroll
            for (int mt = 0; mt < 2; mt++)
                #pragma unroll
                for (int nt = 0; nt < 4; nt++) {
                    MMA16816(d[mt][nt], ah[mt], bh[nt]);
                    MMA16816(d[mt][nt], ah[mt], bl[nt]);
                    MMA16816(d[mt][nt], al[mt], bh[nt]);
                }
            phase++;
        }
        __syncthreads();   // SF rewrite in next q must wait for this q's gathers
    }

    // ---- epilogue: bias + store z + fused GroupNorm partial stats ----
    int hr = lane >> 2;
    int op = (lane & 3) * 2;
    float gs[4], gq[4];
    #pragma unroll
    for (int nt = 0; nt < 4; nt++) { gs[nt] = 0.f; gq[nt] = 0.f; }

    #pragma unroll
    for (int mt = 0; mt < 2; mt++) {
        int hh = mrow + mt*16 + hr;
        #pragma unroll
        for (int nt = 0; nt < 4; nt++) {
            int oc = ncol + nt*8 + op;
            float b0 = __ldg(cb + oc), b1 = __ldg(cb + oc + 1);
            float* z0 = g_z + ((b*OCC + oc  )*WW + w)*HH;
            float* z1 = g_z + ((b*OCC + oc+1)*WW + w)*HH;
            float v0 = d[mt][nt][0] + b0;
            float v1 = d[mt][nt][1] + b1;
            float v2 = d[mt][nt][2] + b0;
            float v3 = d[mt][nt][3] + b1;
            z0[hh]     = v0;
            z1[hh]     = v1;
            z0[hh + 8] = v2;
            z1[hh + 8] = v3;
            gs[nt] += v0 + v1 + v2 + v3;
            gq[nt] += v0*v0 + v1*v1 + v2*v2 + v3*v3;
        }
    }

    #pragma unroll
    for (int nt = 0; nt < 4; nt++) {
        #pragma unroll
        for (int o = 0; o < 4; o++) {
            int m = (o == 0) ? 1 : (o == 1) ? 4 : (o == 2) ? 8 : 16;
            gs[nt] += __shfl_xor_sync(0xffffffffu, gs[nt], m);
            gq[nt] += __shfl_xor_sync(0xffffffffu, gq[nt], m);
        }
    }
    if ((lane & ~2) == 0) {
        int gpar = (lane >> 1) & 1;
        #pragma unroll
        for (int nt = 0; nt < 4; nt++) {
            int grp = b*GG + (ncol >> 2) + nt*2 + gpar;
            atomicAdd(&g_gsum[grp], gs[nt]);
            atomicAdd(&g_gsq [grp], gq[nt]);
        }
    }
}

// ---------------------------------------------------------------------------
// Kernel C: GroupNorm finalize + gamma/beta + ReLU (float4 vectorized)
// ---------------------------------------------------------------------------
__global__ void __launch_bounds__(256) gn_kernel(
    const float* __restrict__ gn_g,
    const float* __restrict__ gn_b,
    float* __restrict__ out)
{
    int i4 = blockIdx.x * 256 + threadIdx.x;
    if (i4 >= BB*OCC*WH/4) return;
    int base = i4 * 4;
    int oc = (base / WH) % OCC;
    int b  = base / (OCC*WH);
    int grp = b*GG + (oc >> 2);
    const float invn = 1.f / (float)(4*WH);
    float mu  = g_gsum[grp] * invn;
    float var = g_gsq [grp] * invn - mu*mu;
    float rs  = rsqrtf(var + EPSF);
    float sc = rs * __ldg(gn_g + oc);
    float sh = __ldg(gn_b + oc) - mu * sc;
    float4 z = ((const float4*)g_z)[i4];
    float4 o;
    o.x = fmaxf(z.x*sc + sh, 0.f);
    o.y = fmaxf(z.y*sc + sh, 0.f);
    o.z = fmaxf(z.z*sc + sh, 0.f);
    o.w = fmaxf(z.w*sc + sh, 0.f);
    ((float4*)out)[i4] = o;
}

// ---------------------------------------------------------------------------
extern "C" void kernel_launch(void* const* d_in, const int* in_sizes, int n_in,
                              void* d_out, int out_size)
{
    const float* f        = (const float*)d_in[0];
    const float* offset_w = (const float*)d_in[1];
    const float* offset_b = (const float*)d_in[2];
    const float* bn_gamma = (const float*)d_in[3];
    const float* bn_beta  = (const float*)d_in[4];
    const float* bn_mean  = (const float*)d_in[5];
    const float* bn_var   = (const float*)d_in[6];
    const float* conv_w   = (const float*)d_in[7];
    const float* conv_b   = (const float*)d_in[8];
    const float* gn_gamma = (const float*)d_in[9];
    const float* gn_beta  = (const float*)d_in[10];
    float* out = (float*)d_out;

    cudaFuncSetAttribute(dsconv_mma_kernel,
                         cudaFuncAttributeMaxDynamicSharedMemorySize, S_TOT);

    prep_w_kernel<<<(KK*OCC*CC + 255)/256, 256>>>(conv_w);

    offset_kernel<<<(BB*WW*HH)/128, 128>>>(f, offset_w, offset_b,
                                           bn_gamma, bn_beta, bn_mean, bn_var);

    dim3 gridB(WW, BB);
    dsconv_mma_kernel<<<gridB, 256, S_TOT>>>(f, conv_b);

    int total4 = BB*OCC*WH/4;
    gn_kernel<<<(total4 + 255)/256, 256>>>(gn_gamma, gn_beta, out);
}